// round 4
// baseline (speedup 1.0000x reference)
#include <cuda_runtime.h>
#include <cuda_bf16.h>

#define HH 256
#define WW 256
#define NIMG (64*21)
#define TILE_X 128
#define TILE_Y 64
#define SROWS (TILE_Y + 8)    // 72
#define SSTRIDE (TILE_X + 8)  // 136 floats per smem row (544B, 16B-aligned)

__global__ __launch_bounds__(256, 2)
void heatmap_sepconv_kernel(const int* __restrict__ coords,
                            const float* __restrict__ noise,
                            const float* __restrict__ k2d,
                            float* __restrict__ out)
{
    __shared__ float sk[81];
    __shared__ __align__(16) float sin_[SROWS * SSTRIDE];  // 39168 B

    const int tid = threadIdx.x;
    const int img = blockIdx.z;
    const int x0 = blockIdx.x * TILE_X;
    const int y0 = blockIdx.y * TILE_Y;

    if (tid < 81) sk[tid] = k2d[tid];

    const int cx = coords[2 * img];
    const int cy = coords[2 * img + 1];
    const float gval = 1.0f / __ldg(&k2d[40]);  // peak value = 1/max(kernel2d)

    const float* __restrict__ np = noise + (size_t)img * (HH * WW);

    // Load haloed tile: scaled noise, zero padding, peak injection.
    #pragma unroll 4
    for (int s = tid; s < SROWS * SSTRIDE; s += 256) {
        int ir = s / SSTRIDE;
        int ic = s - ir * SSTRIDE;
        int gy = y0 - 4 + ir;
        int gx = x0 - 4 + ic;
        float v = 0.0f;
        if (gy >= 0 && gy < HH && gx >= 0 && gx < WW) {
            v = 0.01f * np[gy * WW + gx];
            if (gy == cy && gx == cx) v = gval;
        }
        sin_[s] = v;
    }
    __syncthreads();

    // 1D gaussian from row sums of the 2D kernel (broadcast LDS, cheap).
    float g[9];
    #pragma unroll
    for (int i = 0; i < 9; i++) {
        float s = 0.0f;
        #pragma unroll
        for (int j = 0; j < 9; j++) s += sk[i * 9 + j];
        g[i] = s;
    }

    // Thread owns 4 consecutive columns x 8 output rows.
    const int tx = tid & 31;        // 32 column groups
    const int ty = tid >> 5;        // 8 row groups
    const int cbase = tx * 4;       // 0..124 (16B-aligned in smem row)
    const int r0 = ty * 8;          // 0..56

    // Horizontal pass: 16 tmp rows (8 outputs + 8 halo) kept in registers.
    float tmp[16][4];
    #pragma unroll
    for (int rr = 0; rr < 16; rr++) {
        const float* row = &sin_[(r0 + rr) * SSTRIDE + cbase];
        float4 a = *(const float4*)(row);
        float4 b = *(const float4*)(row + 4);
        float4 c = *(const float4*)(row + 8);
        float v[12] = {a.x, a.y, a.z, a.w, b.x, b.y, b.z, b.w, c.x, c.y, c.z, c.w};
        #pragma unroll
        for (int cc = 0; cc < 4; cc++) {
            float s = 0.0f;
            #pragma unroll
            for (int j = 0; j < 9; j++) s = fmaf(g[j], v[cc + j], s);
            tmp[rr][cc] = s;
        }
    }

    // Vertical pass: register-only sliding window, ReLU, float4 stores.
    const size_t obase = (size_t)img * (HH * WW);
    #pragma unroll
    for (int rr = 0; rr < 8; rr++) {
        float acc0 = 0.f, acc1 = 0.f, acc2 = 0.f, acc3 = 0.f;
        #pragma unroll
        for (int i = 0; i < 9; i++) {
            acc0 = fmaf(g[i], tmp[rr + i][0], acc0);
            acc1 = fmaf(g[i], tmp[rr + i][1], acc1);
            acc2 = fmaf(g[i], tmp[rr + i][2], acc2);
            acc3 = fmaf(g[i], tmp[rr + i][3], acc3);
        }
        int gy = y0 + r0 + rr;
        float4 ov = make_float4(fmaxf(acc0, 0.f), fmaxf(acc1, 0.f),
                                fmaxf(acc2, 0.f), fmaxf(acc3, 0.f));
        *(float4*)(out + obase + (size_t)gy * WW + x0 + cbase) = ov;
    }
}

extern "C" void kernel_launch(void* const* d_in, const int* in_sizes, int n_in,
                              void* d_out, int out_size)
{
    // Identify inputs by element count (robust to ordering):
    //   coords: 64*21*2 = 2688 int32; kernel2d: 81 fp32; noise: 64*21*256*256 fp32.
    const int* coords = nullptr;
    const float* noise = nullptr;
    const float* k2d = nullptr;
    for (int i = 0; i < n_in; i++) {
        if (in_sizes[i] == 81)            k2d    = (const float*)d_in[i];
        else if (in_sizes[i] == 64*21*2)  coords = (const int*)d_in[i];
        else                              noise  = (const float*)d_in[i];
    }

    dim3 grid(WW / TILE_X, HH / TILE_Y, NIMG);
    heatmap_sepconv_kernel<<<grid, 256>>>(coords, noise, k2d, (float*)d_out);
}

// round 5
// speedup vs baseline: 1.0021x; 1.0021x over previous
#include <cuda_runtime.h>
#include <cuda_bf16.h>

#define HH 256
#define WW 256
#define NIMG (64*21)
#define TILE_X 128
#define TILE_Y 64
#define SROWS (TILE_Y + 8)    // 72
#define SSTRIDE (TILE_X + 8)  // 136 floats per smem row (544B, 16B-aligned)

__global__ __launch_bounds__(256, 2)
void heatmap_sepconv_kernel(const int* __restrict__ coords,
                            const float* __restrict__ noise,
                            const float* __restrict__ k2d,
                            float* __restrict__ out)
{
    __shared__ float sk[81];
    __shared__ __align__(16) float sin_[SROWS * SSTRIDE];  // 39168 B

    const int tid = threadIdx.x;
    const int img = blockIdx.z;
    const int x0 = blockIdx.x * TILE_X;
    const int y0 = blockIdx.y * TILE_Y;

    if (tid < 81) sk[tid] = k2d[tid];

    const int cx = coords[2 * img];
    const int cy = coords[2 * img + 1];
    const float gval = 1.0f / __ldg(&k2d[40]);  // peak value = 1/max(kernel2d)

    const float* __restrict__ np = noise + (size_t)img * (HH * WW);

    // Load haloed tile: scaled noise, zero padding, peak injection.
    #pragma unroll 4
    for (int s = tid; s < SROWS * SSTRIDE; s += 256) {
        int ir = s / SSTRIDE;
        int ic = s - ir * SSTRIDE;
        int gy = y0 - 4 + ir;
        int gx = x0 - 4 + ic;
        float v = 0.0f;
        if (gy >= 0 && gy < HH && gx >= 0 && gx < WW) {
            v = 0.01f * np[gy * WW + gx];
            if (gy == cy && gx == cx) v = gval;
        }
        sin_[s] = v;
    }
    __syncthreads();

    // 1D gaussian from row sums of the 2D kernel (broadcast LDS, cheap).
    float g[9];
    #pragma unroll
    for (int i = 0; i < 9; i++) {
        float s = 0.0f;
        #pragma unroll
        for (int j = 0; j < 9; j++) s += sk[i * 9 + j];
        g[i] = s;
    }

    // Thread owns 4 consecutive columns x 8 output rows.
    const int tx = tid & 31;        // 32 column groups
    const int ty = tid >> 5;        // 8 row groups
    const int cbase = tx * 4;       // 0..124 (16B-aligned in smem row)
    const int r0 = ty * 8;          // 0..56

    // Horizontal pass: 16 tmp rows (8 outputs + 8 halo) kept in registers.
    float tmp[16][4];
    #pragma unroll
    for (int rr = 0; rr < 16; rr++) {
        const float* row = &sin_[(r0 + rr) * SSTRIDE + cbase];
        float4 a = *(const float4*)(row);
        float4 b = *(const float4*)(row + 4);
        float4 c = *(const float4*)(row + 8);
        float v[12] = {a.x, a.y, a.z, a.w, b.x, b.y, b.z, b.w, c.x, c.y, c.z, c.w};
        #pragma unroll
        for (int cc = 0; cc < 4; cc++) {
            float s = 0.0f;
            #pragma unroll
            for (int j = 0; j < 9; j++) s = fmaf(g[j], v[cc + j], s);
            tmp[rr][cc] = s;
        }
    }

    // Vertical pass: register-only sliding window, ReLU, float4 stores.
    const size_t obase = (size_t)img * (HH * WW);
    #pragma unroll
    for (int rr = 0; rr < 8; rr++) {
        float acc0 = 0.f, acc1 = 0.f, acc2 = 0.f, acc3 = 0.f;
        #pragma unroll
        for (int i = 0; i < 9; i++) {
            acc0 = fmaf(g[i], tmp[rr + i][0], acc0);
            acc1 = fmaf(g[i], tmp[rr + i][1], acc1);
            acc2 = fmaf(g[i], tmp[rr + i][2], acc2);
            acc3 = fmaf(g[i], tmp[rr + i][3], acc3);
        }
        int gy = y0 + r0 + rr;
        float4 ov = make_float4(fmaxf(acc0, 0.f), fmaxf(acc1, 0.f),
                                fmaxf(acc2, 0.f), fmaxf(acc3, 0.f));
        *(float4*)(out + obase + (size_t)gy * WW + x0 + cbase) = ov;
    }
}

extern "C" void kernel_launch(void* const* d_in, const int* in_sizes, int n_in,
                              void* d_out, int out_size)
{
    // Identify inputs by element count (robust to ordering):
    //   coords: 64*21*2 = 2688 int32; kernel2d: 81 fp32; noise: 64*21*256*256 fp32.
    const int* coords = nullptr;
    const float* noise = nullptr;
    const float* k2d = nullptr;
    for (int i = 0; i < n_in; i++) {
        if (in_sizes[i] == 81)            k2d    = (const float*)d_in[i];
        else if (in_sizes[i] == 64*21*2)  coords = (const int*)d_in[i];
        else                              noise  = (const float*)d_in[i];
    }

    dim3 grid(WW / TILE_X, HH / TILE_Y, NIMG);
    heatmap_sepconv_kernel<<<grid, 256>>>(coords, noise, k2d, (float*)d_out);
}

// round 6
// speedup vs baseline: 1.0034x; 1.0013x over previous
#include <cuda_runtime.h>
#include <cuda_bf16.h>

#define HH 256
#define WW 256
#define NIMG (64*21)
#define TILE_X 128
#define TILE_Y 64
#define SROWS (TILE_Y + 8)    // 72
#define SSTRIDE (TILE_X + 8)  // 136 floats per smem row (544B, 16B-aligned)

__global__ __launch_bounds__(256, 2)
void heatmap_sepconv_kernel(const int* __restrict__ coords,
                            const float* __restrict__ noise,
                            const float* __restrict__ k2d,
                            float* __restrict__ out)
{
    __shared__ float sk[81];
    __shared__ __align__(16) float sin_[SROWS * SSTRIDE];  // 39168 B

    const int tid = threadIdx.x;
    const int img = blockIdx.z;
    const int x0 = blockIdx.x * TILE_X;
    const int y0 = blockIdx.y * TILE_Y;

    if (tid < 81) sk[tid] = k2d[tid];

    const int cx = coords[2 * img];
    const int cy = coords[2 * img + 1];
    const float gval = 1.0f / __ldg(&k2d[40]);  // peak value = 1/max(kernel2d)

    const float* __restrict__ np = noise + (size_t)img * (HH * WW);

    // Load haloed tile: scaled noise, zero padding, peak injection.
    #pragma unroll 4
    for (int s = tid; s < SROWS * SSTRIDE; s += 256) {
        int ir = s / SSTRIDE;
        int ic = s - ir * SSTRIDE;
        int gy = y0 - 4 + ir;
        int gx = x0 - 4 + ic;
        float v = 0.0f;
        if (gy >= 0 && gy < HH && gx >= 0 && gx < WW) {
            v = 0.01f * np[gy * WW + gx];
            if (gy == cy && gx == cx) v = gval;
        }
        sin_[s] = v;
    }
    __syncthreads();

    // 1D gaussian from row sums of the 2D kernel (broadcast LDS, cheap).
    float g[9];
    #pragma unroll
    for (int i = 0; i < 9; i++) {
        float s = 0.0f;
        #pragma unroll
        for (int j = 0; j < 9; j++) s += sk[i * 9 + j];
        g[i] = s;
    }

    // Thread owns 4 consecutive columns x 8 output rows.
    const int tx = tid & 31;        // 32 column groups
    const int ty = tid >> 5;        // 8 row groups
    const int cbase = tx * 4;       // 0..124 (16B-aligned in smem row)
    const int r0 = ty * 8;          // 0..56

    // Horizontal pass: 16 tmp rows (8 outputs + 8 halo) kept in registers.
    float tmp[16][4];
    #pragma unroll
    for (int rr = 0; rr < 16; rr++) {
        const float* row = &sin_[(r0 + rr) * SSTRIDE + cbase];
        float4 a = *(const float4*)(row);
        float4 b = *(const float4*)(row + 4);
        float4 c = *(const float4*)(row + 8);
        float v[12] = {a.x, a.y, a.z, a.w, b.x, b.y, b.z, b.w, c.x, c.y, c.z, c.w};
        #pragma unroll
        for (int cc = 0; cc < 4; cc++) {
            float s = 0.0f;
            #pragma unroll
            for (int j = 0; j < 9; j++) s = fmaf(g[j], v[cc + j], s);
            tmp[rr][cc] = s;
        }
    }

    // Vertical pass: register-only sliding window, ReLU, float4 stores.
    const size_t obase = (size_t)img * (HH * WW);
    #pragma unroll
    for (int rr = 0; rr < 8; rr++) {
        float acc0 = 0.f, acc1 = 0.f, acc2 = 0.f, acc3 = 0.f;
        #pragma unroll
        for (int i = 0; i < 9; i++) {
            acc0 = fmaf(g[i], tmp[rr + i][0], acc0);
            acc1 = fmaf(g[i], tmp[rr + i][1], acc1);
            acc2 = fmaf(g[i], tmp[rr + i][2], acc2);
            acc3 = fmaf(g[i], tmp[rr + i][3], acc3);
        }
        int gy = y0 + r0 + rr;
        float4 ov = make_float4(fmaxf(acc0, 0.f), fmaxf(acc1, 0.f),
                                fmaxf(acc2, 0.f), fmaxf(acc3, 0.f));
        *(float4*)(out + obase + (size_t)gy * WW + x0 + cbase) = ov;
    }
}

extern "C" void kernel_launch(void* const* d_in, const int* in_sizes, int n_in,
                              void* d_out, int out_size)
{
    // Identify inputs by element count (robust to ordering):
    //   coords: 64*21*2 = 2688 int32; kernel2d: 81 fp32; noise: 64*21*256*256 fp32.
    const int* coords = nullptr;
    const float* noise = nullptr;
    const float* k2d = nullptr;
    for (int i = 0; i < n_in; i++) {
        if (in_sizes[i] == 81)            k2d    = (const float*)d_in[i];
        else if (in_sizes[i] == 64*21*2)  coords = (const int*)d_in[i];
        else                              noise  = (const float*)d_in[i];
    }

    dim3 grid(WW / TILE_X, HH / TILE_Y, NIMG);
    heatmap_sepconv_kernel<<<grid, 256>>>(coords, noise, k2d, (float*)d_out);
}

// round 7
// speedup vs baseline: 1.8712x; 1.8648x over previous
#include <cuda_runtime.h>
#include <cuda_bf16.h>

#define HH 256
#define WW 256
#define NIMG (64*21)
#define TILE_X 128
#define TILE_Y 64
#define SROWS (TILE_Y + 8)    // 72
#define SSTRIDE (TILE_X + 8)  // 136 floats (544B, 16B-aligned rows)

__global__ __launch_bounds__(256, 4)
void heatmap_sepconv_kernel(const int* __restrict__ coords,
                            const float* __restrict__ noise,
                            const float* __restrict__ k2d,
                            float* __restrict__ out)
{
    __shared__ float sk[81];
    __shared__ __align__(16) float sin_[SROWS * SSTRIDE];  // 39168 B

    const int tid = threadIdx.x;
    const int img = blockIdx.z;
    const int x0 = blockIdx.x * TILE_X;
    const int y0 = blockIdx.y * TILE_Y;

    if (tid < 81) sk[tid] = k2d[tid];

    const float* __restrict__ np = noise + (size_t)img * (HH * WW);

    // ---- Main tile load: 9 sweeps of (8 rows x 32 float4), no div, no scaling ----
    {
        const int lrow = tid >> 5;          // 0..7
        const int lcol = (tid & 31) << 2;   // 0..124, gx = x0+lcol is 16B aligned
        #pragma unroll
        for (int rb = 0; rb < SROWS; rb += 8) {
            const int row = rb + lrow;      // 0..71 (72 % 8 == 0)
            const int gy = y0 - 4 + row;
            float4 v = make_float4(0.f, 0.f, 0.f, 0.f);
            if (gy >= 0 && gy < HH)
                v = *(const float4*)(np + gy * WW + x0 + lcol);
            *(float4*)&sin_[row * SSTRIDE + 4 + lcol] = v;
        }
    }
    // ---- Halo columns: 72 rows x (4 left + 4 right) = 576 scalar loads ----
    for (int e = tid; e < SROWS * 8; e += 256) {
        const int row = e >> 3;
        const int c = e & 7;
        const int ic = (c < 4) ? c : (128 + c);
        const int gy = y0 - 4 + row;
        const int gx = x0 - 4 + ic;
        float v = 0.f;
        if (gy >= 0 && gy < HH && gx >= 0 && gx < WW) v = np[gy * WW + gx];
        sin_[row * SSTRIDE + ic] = v;
    }
    __syncthreads();

    // ---- Peak injection: one thread, one write (noise is unscaled, so peak is
    //      100x; the 0.01 global scale is applied at the store). ----
    if (tid == 0) {
        const int cx = coords[2 * img];
        const int cy = coords[2 * img + 1];
        const int lx = cx - (x0 - 4);
        const int ly = cy - (y0 - 4);
        if (lx >= 0 && lx < SSTRIDE && ly >= 0 && ly < SROWS)
            sin_[ly * SSTRIDE + lx] = 100.0f / sk[40];   // (1/max)/0.01
    }
    __syncthreads();

    // 1D gaussian = row sums of 2D kernel (broadcast LDS).
    float g[9];
    #pragma unroll
    for (int i = 0; i < 9; i++) {
        float s = 0.f;
        #pragma unroll
        for (int j = 0; j < 9; j++) s += sk[i * 9 + j];
        g[i] = s;
    }

    // Thread owns 4 columns x 8 output rows; stream 16 input rows and
    // accumulate into acc[8][4] (32 regs instead of tmp[16][4]=64).
    const int tx = tid & 31;
    const int ty = tid >> 5;
    const int cbase = tx * 4;
    const int r0 = ty * 8;

    float acc[8][4];
    #pragma unroll
    for (int r = 0; r < 8; r++)
        #pragma unroll
        for (int cc = 0; cc < 4; cc++) acc[r][cc] = 0.f;

    #pragma unroll
    for (int ir = 0; ir < 16; ir++) {
        const float* row = &sin_[(r0 + ir) * SSTRIDE + cbase];
        float4 a = *(const float4*)(row);
        float4 b = *(const float4*)(row + 4);
        float4 c = *(const float4*)(row + 8);
        float v[12] = {a.x, a.y, a.z, a.w, b.x, b.y, b.z, b.w, c.x, c.y, c.z, c.w};
        float h[4];
        #pragma unroll
        for (int cc = 0; cc < 4; cc++) {
            float s = 0.f;
            #pragma unroll
            for (int j = 0; j < 9; j++) s = fmaf(g[j], v[cc + j], s);
            h[cc] = s;
        }
        #pragma unroll
        for (int r = 0; r < 8; r++) {
            const int i = ir - r;
            if (i >= 0 && i < 9) {
                #pragma unroll
                for (int cc = 0; cc < 4; cc++)
                    acc[r][cc] = fmaf(g[i], h[cc], acc[r][cc]);
            }
        }
    }

    // Store: apply the deferred 0.01 noise scale + ReLU, float4 coalesced.
    const size_t obase = (size_t)img * (HH * WW);
    #pragma unroll
    for (int r = 0; r < 8; r++) {
        const int gy = y0 + r0 + r;
        float4 ov = make_float4(fmaxf(0.01f * acc[r][0], 0.f),
                                fmaxf(0.01f * acc[r][1], 0.f),
                                fmaxf(0.01f * acc[r][2], 0.f),
                                fmaxf(0.01f * acc[r][3], 0.f));
        *(float4*)(out + obase + (size_t)gy * WW + x0 + cbase) = ov;
    }
}

extern "C" void kernel_launch(void* const* d_in, const int* in_sizes, int n_in,
                              void* d_out, int out_size)
{
    const int* coords = nullptr;
    const float* noise = nullptr;
    const float* k2d = nullptr;
    for (int i = 0; i < n_in; i++) {
        if (in_sizes[i] == 81)            k2d    = (const float*)d_in[i];
        else if (in_sizes[i] == 64*21*2)  coords = (const int*)d_in[i];
        else                              noise  = (const float*)d_in[i];
    }

    dim3 grid(WW / TILE_X, HH / TILE_Y, NIMG);
    heatmap_sepconv_kernel<<<grid, 256>>>(coords, noise, k2d, (float*)d_out);
}

// round 8
// speedup vs baseline: 1.9820x; 1.0592x over previous
#include <cuda_runtime.h>
#include <cuda_bf16.h>

#define HH 256
#define WW 256
#define NIMG (64*21)
#define TILE_X 128
#define TILE_Y 64
#define SROWS (TILE_Y + 8)    // 72
#define SSTRIDE (TILE_X + 8)  // 136 floats (544B, 16B-aligned rows)

// Packed f32x2 FMA (Blackwell FFMA2) — ptxas never emits this from C++.
__device__ __forceinline__ float2 ffma2(float2 a, float2 b, float2 c) {
    float2 d;
    asm("fma.rn.f32x2 %0, %1, %2, %3;"
        : "=l"(reinterpret_cast<unsigned long long&>(d))
        : "l"(reinterpret_cast<unsigned long long&>(a)),
          "l"(reinterpret_cast<unsigned long long&>(b)),
          "l"(reinterpret_cast<unsigned long long&>(c)));
    return d;
}

// Gaussian is symmetric: g[j] == g[8-j] bit-exactly (row sums of a symmetric
// outer product). Keep only 5 packed taps.
#define GG(j) gg[((j) < 5) ? (j) : (8 - (j))]

__global__ __launch_bounds__(256, 4)
void heatmap_sepconv_kernel(const int* __restrict__ coords,
                            const float* __restrict__ noise,
                            const float* __restrict__ k2d,
                            float* __restrict__ out)
{
    __shared__ float sk[81];
    __shared__ __align__(16) float sin_[SROWS * SSTRIDE];  // 39168 B

    const int tid = threadIdx.x;
    const int img = blockIdx.z;
    const int x0 = blockIdx.x * TILE_X;
    const int y0 = blockIdx.y * TILE_Y;

    if (tid < 81) sk[tid] = k2d[tid];

    const float* __restrict__ np = noise + (size_t)img * (HH * WW);

    // ---- Main tile load: 9 sweeps of (8 rows x 32 float4), unscaled ----
    {
        const int lrow = tid >> 5;
        const int lcol = (tid & 31) << 2;
        #pragma unroll
        for (int rb = 0; rb < SROWS; rb += 8) {
            const int row = rb + lrow;
            const int gy = y0 - 4 + row;
            float4 v = make_float4(0.f, 0.f, 0.f, 0.f);
            if (gy >= 0 && gy < HH)
                v = *(const float4*)(np + gy * WW + x0 + lcol);
            *(float4*)&sin_[row * SSTRIDE + 4 + lcol] = v;
        }
    }
    // ---- Halo columns: 72 rows x (4 left + 4 right) scalar loads ----
    for (int e = tid; e < SROWS * 8; e += 256) {
        const int row = e >> 3;
        const int c = e & 7;
        const int ic = (c < 4) ? c : (128 + c);
        const int gy = y0 - 4 + row;
        const int gx = x0 - 4 + ic;
        float v = 0.f;
        if (gy >= 0 && gy < HH && gx >= 0 && gx < WW) v = np[gy * WW + gx];
        sin_[row * SSTRIDE + ic] = v;
    }
    __syncthreads();

    // ---- Peak injection (noise unscaled -> peak is 100x; 0.01 applied at store) ----
    if (tid == 0) {
        const int cx = coords[2 * img];
        const int cy = coords[2 * img + 1];
        const int lx = cx - (x0 - 4);
        const int ly = cy - (y0 - 4);
        if (lx >= 0 && lx < SSTRIDE && ly >= 0 && ly < SROWS)
            sin_[ly * SSTRIDE + lx] = 100.0f / sk[40];
    }
    __syncthreads();

    // 1D gaussian = row sums of 2D kernel; pack 5 symmetric taps.
    float2 gg[5];
    #pragma unroll
    for (int i = 0; i < 5; i++) {
        float s = 0.f;
        #pragma unroll
        for (int j = 0; j < 9; j++) s += sk[i * 9 + j];
        gg[i] = make_float2(s, s);
    }

    const int tx = tid & 31;
    const int ty = tid >> 5;
    const int cbase = tx * 4;
    const int r0 = ty * 8;

    // Column-packed accumulators: A[r][0]=(c0,c1), A[r][1]=(c2,c3).
    float2 A[8][2];
    #pragma unroll
    for (int r = 0; r < 8; r++) {
        A[r][0] = make_float2(0.f, 0.f);
        A[r][1] = make_float2(0.f, 0.f);
    }

    // Stream 16 haloed input rows as 8 row-pairs.
    #pragma unroll
    for (int t = 0; t < 8; t++) {
        const float* rowa = &sin_[(r0 + 2 * t) * SSTRIDE + cbase];
        const float* rowb = rowa + SSTRIDE;
        float4 a0 = *(const float4*)(rowa);
        float4 a1 = *(const float4*)(rowa + 4);
        float4 a2 = *(const float4*)(rowa + 8);
        float4 b0 = *(const float4*)(rowb);
        float4 b1 = *(const float4*)(rowb + 4);
        float4 b2 = *(const float4*)(rowb + 8);
        // Row-paired input: v2[j] = (row_a[j], row_b[j])
        float2 v2[12] = {
            {a0.x, b0.x}, {a0.y, b0.y}, {a0.z, b0.z}, {a0.w, b0.w},
            {a1.x, b1.x}, {a1.y, b1.y}, {a1.z, b1.z}, {a1.w, b1.w},
            {a2.x, b2.x}, {a2.y, b2.y}, {a2.z, b2.z}, {a2.w, b2.w}};

        // Horizontal pass: hp[cc] = (h_rowA[cc], h_rowB[cc]) via 9 FFMA2 each.
        float2 hp[4];
        #pragma unroll
        for (int cc = 0; cc < 4; cc++) {
            float2 s = make_float2(0.f, 0.f);
            #pragma unroll
            for (int j = 0; j < 9; j++) s = ffma2(GG(j), v2[cc + j], s);
            hp[cc] = s;
        }

        // Re-pack by columns for the vertical pass (register moves only).
        float2 hap0 = make_float2(hp[0].x, hp[1].x);
        float2 hap1 = make_float2(hp[2].x, hp[3].x);
        float2 hbp0 = make_float2(hp[0].y, hp[1].y);
        float2 hbp1 = make_float2(hp[2].y, hp[3].y);

        // Vertical accumulation: input rows ir=2t (A-half) and 2t+1 (B-half),
        // tap i = ir - r, valid for 0<=i<=8. All bounds compile-time.
        #pragma unroll
        for (int r = 0; r < 8; r++) {
            const int ia = 2 * t - r;
            if (ia >= 0 && ia <= 8) {
                A[r][0] = ffma2(GG(ia), hap0, A[r][0]);
                A[r][1] = ffma2(GG(ia), hap1, A[r][1]);
            }
            const int ib = 2 * t + 1 - r;
            if (ib >= 0 && ib <= 8) {
                A[r][0] = ffma2(GG(ib), hbp0, A[r][0]);
                A[r][1] = ffma2(GG(ib), hbp1, A[r][1]);
            }
        }
    }

    // Store: deferred 0.01 scale + ReLU (max(x,0)*0.01 == max(0.01x,0)).
    const size_t obase = (size_t)img * (HH * WW);
    #pragma unroll
    for (int r = 0; r < 8; r++) {
        const int gy = y0 + r0 + r;
        float4 ov = make_float4(fmaxf(A[r][0].x, 0.f) * 0.01f,
                                fmaxf(A[r][0].y, 0.f) * 0.01f,
                                fmaxf(A[r][1].x, 0.f) * 0.01f,
                                fmaxf(A[r][1].y, 0.f) * 0.01f);
        *(float4*)(out + obase + (size_t)gy * WW + x0 + cbase) = ov;
    }
}

extern "C" void kernel_launch(void* const* d_in, const int* in_sizes, int n_in,
                              void* d_out, int out_size)
{
    const int* coords = nullptr;
    const float* noise = nullptr;
    const float* k2d = nullptr;
    for (int i = 0; i < n_in; i++) {
        if (in_sizes[i] == 81)            k2d    = (const float*)d_in[i];
        else if (in_sizes[i] == 64*21*2)  coords = (const int*)d_in[i];
        else                              noise  = (const float*)d_in[i];
    }

    dim3 grid(WW / TILE_X, HH / TILE_Y, NIMG);
    heatmap_sepconv_kernel<<<grid, 256>>>(coords, noise, k2d, (float*)d_out);
}